// round 1
// baseline (speedup 1.0000x reference)
#include <cuda_runtime.h>
#include <cstdint>

// Problem constants
#define SHAPE_  64
#define NHEADS  16
#define EMB     64
#define BATCH   8
#define SEQ     (SHAPE_ * SHAPE_)      // 4096
#define NW      127                    // 2*SHAPE_-1
#define SSTRIDE (NHEADS * EMB)         // 1024 floats between consecutive s

// Block decomposition: one block per (b, h, e-half). 256 blocks total.
#define EH   32      // e elements per block
#define TPB  512     // threads: el = t&31 (local e), g = t>>5 (0..15)

__global__ __launch_bounds__(TPB, 2)
void fftbias2d_fused(const float* __restrict__ v,
                     const float* __restrict__ w,
                     float* __restrict__ out) {
    const int blk = blockIdx.x;
    const int eh  = blk & 1;            // which 32-wide e half
    const int h   = (blk >> 1) & (NHEADS - 1);
    const int b   = blk >> 5;

    const int t  = threadIdx.x;
    const int el = t & (EH - 1);        // local e (0..31)
    const int g  = t >> 5;              // group (0..15)

    __shared__ __align__(16) float w_ext[128];
    __shared__ __align__(16) float f_sh[64][EH];   // f[s2][e] -> later RxV[j][e]
    __shared__ __align__(16) float u_sh[64][EH];   // u[s1][e] -> later RxU[i][e]
    __shared__ __align__(16) float red[2][16][EH]; // staging for u reduction

    // Load per-head filter, extended so K[j][s] = w_ext[j + 64 - s]
    // (index in [1,127]; 127 wraps to w[0]).
    if (t < NW)  w_ext[t]   = w[h * NW + t];
    if (t == NW) w_ext[127] = w[h * NW + 0];

    // Base pointer for this (b, h, e): element (s1,s2) at + (s1*64+s2)*SSTRIDE
    const float* vbase = v + ((size_t)b * SEQ * NHEADS + h) * EMB + eh * EH + el;

    // ---------------- Phase 1: stream v, build f (regs) and u (shared) -----
    float facc0 = 0.f, facc1 = 0.f, facc2 = 0.f, facc3 = 0.f;  // s2 = g + 16k

    for (int s1b = 0; s1b < 32; ++s1b) {
        const int s1a = 2 * s1b;
        float a0 = 0.f, a1 = 0.f;
        {
            const size_t r0 = (size_t)(s1a * 64) * SSTRIDE;
            const size_t r1 = (size_t)((s1a + 1) * 64) * SSTRIDE;
            float v00 = vbase[r0 + (size_t)(g +  0) * SSTRIDE];
            float v01 = vbase[r0 + (size_t)(g + 16) * SSTRIDE];
            float v02 = vbase[r0 + (size_t)(g + 32) * SSTRIDE];
            float v03 = vbase[r0 + (size_t)(g + 48) * SSTRIDE];
            float v10 = vbase[r1 + (size_t)(g +  0) * SSTRIDE];
            float v11 = vbase[r1 + (size_t)(g + 16) * SSTRIDE];
            float v12 = vbase[r1 + (size_t)(g + 32) * SSTRIDE];
            float v13 = vbase[r1 + (size_t)(g + 48) * SSTRIDE];
            facc0 += v00 + v10;
            facc1 += v01 + v11;
            facc2 += v02 + v12;
            facc3 += v03 + v13;
            a0 = v00 + v01 + v02 + v03;
            a1 = v10 + v11 + v12 + v13;
        }
        red[0][g][el] = a0;
        red[1][g][el] = a1;
        __syncthreads();
        if (t < 2 * EH) {               // 64 reducer threads
            const int ss = t >> 5;      // which of the 2 s1 rows
            const int ee = t & (EH - 1);
            float s = 0.f;
            #pragma unroll
            for (int gg = 0; gg < 16; ++gg) s += red[ss][gg][ee];
            u_sh[s1a + ss][ee] = s;
        }
        __syncthreads();
    }
    f_sh[g +  0][el] = facc0;
    f_sh[g + 16][el] = facc1;
    f_sh[g + 32][el] = facc2;
    f_sh[g + 48][el] = facc3;
    __syncthreads();

    // ---------------- Phase 2: RxV / RxU matvecs (registers) ---------------
    // rv[k] = sum_s w_ext[(g+16k) + 64 - s] * f_sh[s][el]   (j = g+16k)
    float rv0 = 0.f, rv1 = 0.f, rv2 = 0.f, rv3 = 0.f;
    float ru0 = 0.f, ru1 = 0.f, ru2 = 0.f, ru3 = 0.f;
    #pragma unroll 4
    for (int s = 0; s < 64; ++s) {
        const float fv = f_sh[s][el];
        const float uv = u_sh[s][el];
        const int base = g + 64 - s;
        const float wv0 = w_ext[base +  0];
        const float wv1 = w_ext[base + 16];
        const float wv2 = w_ext[base + 32];
        const float wv3 = w_ext[base + 48];
        rv0 += wv0 * fv;  ru0 += wv0 * uv;
        rv1 += wv1 * fv;  ru1 += wv1 * uv;
        rv2 += wv2 * fv;  ru2 += wv2 * uv;
        rv3 += wv3 * fv;  ru3 += wv3 * uv;
    }
    __syncthreads();
    f_sh[g +  0][el] = rv0;  u_sh[g +  0][el] = ru0;
    f_sh[g + 16][el] = rv1;  u_sh[g + 16][el] = ru1;
    f_sh[g + 32][el] = rv2;  u_sh[g + 32][el] = ru2;
    f_sh[g + 48][el] = rv3;  u_sh[g + 48][el] = ru3;
    __syncthreads();

    // ---------------- Phase 3: out[b, s1*64+s2, h, e] = RxV[s2]+RxU[s1] ----
    // thread: eq = t&7 (4 e's), s2 = t>>3 (0..63); float4 stores.
    const int eq = t & 7;
    const int s2 = t >> 3;
    const float4 fv4 = *(const float4*)&f_sh[s2][eq * 4];
    float* obase = out + ((size_t)b * SEQ * NHEADS + h) * EMB + eh * EH + eq * 4;
    #pragma unroll 4
    for (int s1 = 0; s1 < 64; ++s1) {
        const float4 uv4 = *(const float4*)&u_sh[s1][eq * 4];
        float4 o;
        o.x = fv4.x + uv4.x;
        o.y = fv4.y + uv4.y;
        o.z = fv4.z + uv4.z;
        o.w = fv4.w + uv4.w;
        *(float4*)(obase + (size_t)(s1 * 64 + s2) * SSTRIDE) = o;
    }
}

extern "C" void kernel_launch(void* const* d_in, const int* in_sizes, int n_in,
                              void* d_out, int out_size) {
    (void)in_sizes; (void)n_in; (void)out_size;
    const float* v = (const float*)d_in[0];   // [8, 4096, 16, 64] f32
    const float* w = (const float*)d_in[1];   // [1, 16, 127]      f32
    float* o = (float*)d_out;                 // [8, 4096, 16, 64] f32
    fftbias2d_fused<<<BATCH * NHEADS * 2, TPB>>>(v, w, o);
}